// round 16
// baseline (speedup 1.0000x reference)
#include <cuda_runtime.h>
#include <math.h>
#include <stdint.h>

// Problem constants
#define BB    256
#define HH    6
#define NN    2048
#define MM    64
#define DIN   128
#define WFLAT 12288          // H*N
#define DCAT  12416
#define DOUT  384
#define Y_N   1152           // 3*DOUT
#define MEM_ELEMS 131072     // N*M per batch
#define OUT_MEM_TOTAL 33554432  // B*N*M

// GEMM config: CTA 128x64, 8 warps x (64x16) tile, BKT=32, cp.async, 256 thr
#define SPLITK 12
#define BKT 32
#define BMT 128
#define BNT 64
#define ASTR 36
#define BSTR 72
#define A_TILE_F (BMT * ASTR)
#define B_TILE_F (BKT * BSTR)
#define GEMM_SMEM_BYTES ((2 * (A_TILE_F + B_TILE_F)) * 4)   // 55296

// Scratch (static device memory; no allocation)
__device__ float g_Ypart[SPLITK * (size_t)BB * Y_N];  // 14.2 MB
__device__ float g_Ks[BB * DOUT];
__device__ float g_Es[BB * DOUT];
__device__ float g_As[BB * DOUT];
__device__ float g_S[(size_t)BB * NN * 8];            // 16.8 MB exp-scores [b][n][8]
__device__ float g_psum[BB * 2 * HH];                 // per-(b,half,h) partial sums

__device__ __forceinline__ unsigned s2u(const void* p) {
    return (unsigned)__cvta_generic_to_shared(p);
}

__device__ __forceinline__ void cpa16(uint32_t dst, const void* src) {
    asm volatile("cp.async.cg.shared.global [%0], [%1], 16;" :: "r"(dst), "l"(src));
}
#define CP_COMMIT() asm volatile("cp.async.commit_group;" ::: "memory")
#define CP_WAIT1()  asm volatile("cp.async.wait_group 1;" ::: "memory")

#define MMA_TF32(c, a, b0, b1)                                                     \
    asm volatile(                                                                  \
        "mma.sync.aligned.m16n8k8.row.col.f32.tf32.tf32.f32 "                      \
        "{%0,%1,%2,%3},{%4,%5,%6,%7},{%8,%9},{%0,%1,%2,%3};"                       \
        : "+f"(c[0]), "+f"(c[1]), "+f"(c[2]), "+f"(c[3])                           \
        : "r"(a[0]), "r"(a[1]), "r"(a[2]), "r"(a[3]), "r"(b0), "r"(b1))

#define LDSM_X4(r, addr)                                                           \
    asm volatile("ldmatrix.sync.aligned.m8n8.x4.shared.b16 {%0,%1,%2,%3}, [%4];"   \
                 : "=r"(r[0]), "=r"(r[1]), "=r"(r[2]), "=r"(r[3]) : "r"(addr))

// ---------------------------------------------------------------------------
// K1: split-K tf32 GEMM  Y[256,1152] = x[256,12416] @ [Wk|We|Wa]
// grid (2, 18, 12), 256 threads (8 warps, 64x16 warp tiles).
// ---------------------------------------------------------------------------
__global__ __launch_bounds__(256) void gemm_kernel(
    const float* __restrict__ xw, const float* __restrict__ xin,
    const float* __restrict__ Wk, const float* __restrict__ We,
    const float* __restrict__ Wa)
{
    extern __shared__ float smf[];
    float* As[2] = {smf, smf + A_TILE_F};
    float* Bs[2] = {smf + 2 * A_TILE_F, smf + 2 * A_TILE_F + B_TILE_F};
    const uint32_t sA32[2] = {s2u(As[0]), s2u(As[1])};
    const uint32_t sB32[2] = {s2u(Bs[0]), s2u(Bs[1])};

    const int tid = threadIdx.x;
    const int mt = blockIdx.x, nt = blockIdx.y, z = blockIdx.z;
    const int m0 = mt * BMT;
    const int mat = nt / 6;
    const int n0col = (nt % 6) * BNT;
    const float* __restrict__ Wp = (mat == 0) ? Wk : ((mat == 1) ? We : Wa);

    // Uneven split over 388 K-tiles: z<4 -> 33 tiles, else 32
    const int baseT = z * 32 + min(z, 4);
    const int cnt   = 32 + (z < 4 ? 1 : 0);
    const int k0    = baseT * BKT;

    const int wid = tid >> 5, lane = tid & 31;
    const int g = lane >> 2, t = lane & 3;
    const int wm = (wid & 1) * 64, wn = (wid >> 1) * 16;

    const int aRowOff = (lane & 15) * ASTR + (lane >> 4) * 4;

    // 256-thread async-copy coordinates
    const int arow = tid >> 3;          // 0..31; rows arow + i*32 (i<4)
    const int ac4  = (tid & 7) * 4;
    const int brow = tid >> 4;          // 0..15; rows brow + i*16 (i<2)
    const int bc4  = (tid & 15) * 4;

    float acc[4][2][4];
#pragma unroll
    for (int i = 0; i < 4; i++)
#pragma unroll
        for (int j = 0; j < 2; j++)
#pragma unroll
            for (int q = 0; q < 4; q++) acc[i][j][q] = 0.0f;

#define LOADT(it)                                                                  \
    do {                                                                           \
        const int buf = (it) & 1;                                                  \
        int kb = k0 + (it) * BKT;                                                  \
        int kg = kb + ac4;                                                         \
        _Pragma("unroll")                                                          \
        for (int i = 0; i < 4; i++) {                                              \
            int row = arow + i * 32;                                               \
            uint32_t dst = sA32[buf] + 4u * (row * ASTR + ac4);                    \
            const float* src = (kg < WFLAT)                                        \
                ? (xw + (size_t)(m0 + row) * WFLAT + kg)                           \
                : (xin + (size_t)(m0 + row) * DIN + (kg - WFLAT));                 \
            cpa16(dst, src);                                                       \
        }                                                                          \
        _Pragma("unroll")                                                          \
        for (int i = 0; i < 2; i++) {                                              \
            int kr = brow + i * 16;                                                \
            uint32_t dst = sB32[buf] + 4u * (kr * BSTR + bc4);                     \
            cpa16(dst, Wp + (size_t)(kb + kr) * DOUT + n0col + bc4);               \
        }                                                                          \
    } while (0)

    LOADT(0);
    CP_COMMIT();
    if (cnt > 1) LOADT(1);
    CP_COMMIT();

    for (int it = 0; it < cnt; ++it) {
        CP_WAIT1();
        __syncthreads();

        const int bf = it & 1;
        const uint32_t sA = sA32[bf];
        const float* __restrict__ Bsf = Bs[bf];
#pragma unroll
        for (int ko = 0; ko < BKT; ko += 8) {
            unsigned af[4][4];
#pragma unroll
            for (int mf = 0; mf < 4; mf++) {
                unsigned addr = sA + 4u * ((wm + mf * 16) * ASTR + aRowOff + ko);
                LDSM_X4(af[mf], addr);
            }
            unsigned bfr[2][2];
#pragma unroll
            for (int nf = 0; nf < 2; nf++) {
                int c0 = wn + nf * 8 + g;
                bfr[nf][0] = __float_as_uint(Bsf[(ko + t) * BSTR + c0]);
                bfr[nf][1] = __float_as_uint(Bsf[(ko + t + 4) * BSTR + c0]);
            }
#pragma unroll
            for (int mf = 0; mf < 4; mf++)
#pragma unroll
                for (int nf = 0; nf < 2; nf++)
                    MMA_TF32(acc[mf][nf], af[mf], bfr[nf][0], bfr[nf][1]);
        }

        __syncthreads();
        if (it + 2 < cnt) LOADT(it + 2);
        CP_COMMIT();
    }

    float* yp = g_Ypart + (size_t)z * (BB * Y_N);
#pragma unroll
    for (int mf = 0; mf < 4; mf++) {
#pragma unroll
        for (int nf = 0; nf < 2; nf++) {
            int row = m0 + wm + mf * 16 + g;
            int col = nt * BNT + wn + nf * 8 + 2 * t;
            float2 v0 = make_float2(acc[mf][nf][0], acc[mf][nf][1]);
            float2 v1 = make_float2(acc[mf][nf][2], acc[mf][nf][3]);
            *(float2*)(yp + (size_t)row * Y_N + col) = v0;
            *(float2*)(yp + (size_t)(row + 8) * Y_N + col) = v1;
        }
    }
#undef LOADT
}

// ---------------------------------------------------------------------------
// K1b: reduce split-K partials, add bias, apply sigmoid for e/a
// ---------------------------------------------------------------------------
__global__ void reduce_act_kernel(const float* __restrict__ bk,
                                  const float* __restrict__ be,
                                  const float* __restrict__ ba)
{
    int idx = blockIdx.x * blockDim.x + threadIdx.x;
    float s = 0.0f;
#pragma unroll
    for (int z = 0; z < SPLITK; z++)
        s += g_Ypart[(size_t)z * (BB * Y_N) + idx];
    int row = idx / Y_N;
    int col = idx - row * Y_N;
    int mat = col / DOUT;
    int c = col - mat * DOUT;
    if (mat == 0) {
        g_Ks[row * DOUT + c] = s + bk[c];
    } else if (mat == 1) {
        float v = s + be[c];
        g_Es[row * DOUT + c] = 1.0f / (1.0f + __expf(-v));
    } else {
        float v = s + ba[c];
        g_As[row * DOUT + c] = 1.0f / (1.0f + __expf(-v));
    }
}

// ---------------------------------------------------------------------------
// K2a: exp(cosine scores) -> g_S[b][n][8], plus per-(b,half,head) sums.
// Scores bounded in [-1,1] so exp without max-subtraction is safe.
// grid (2, 256), 256 threads (8 warps), ~36 KB smem
// ---------------------------------------------------------------------------
#define TSTRIDE 68
__global__ __launch_bounds__(256) void scores_kernel(
    const float* __restrict__ memory)
{
    __shared__ float kn[DOUT];
    __shared__ float tile[8 * 16 * TSTRIDE];
    __shared__ float redp[8][8];   // [warp][head]

    const int b = blockIdx.y;
    const int half = blockIdx.x;
    const int tid = threadIdx.x, wid = tid >> 5, lane = tid & 31;
    const int g = lane >> 2, t = lane & 3;

    // normalized k
    if (wid < HH) {
        float k0 = g_Ks[b * DOUT + wid * 64 + 2 * lane];
        float k1 = g_Ks[b * DOUT + wid * 64 + 2 * lane + 1];
        float ss = k0 * k0 + k1 * k1;
#pragma unroll
        for (int o = 16; o > 0; o >>= 1) ss += __shfl_xor_sync(0xffffffffu, ss, o);
        float rn = rsqrtf(ss);
        kn[wid * 64 + 2 * lane]     = k0 * rn;
        kn[wid * 64 + 2 * lane + 1] = k1 * rn;
    }
    __syncthreads();

    // B fragments (cols 6,7 zero)
    unsigned kb0[8], kb1[8];
#pragma unroll
    for (int c = 0; c < 8; c++) {
        float v0 = (g < HH) ? kn[g * 64 + c * 8 + t] : 0.0f;
        float v1 = (g < HH) ? kn[g * 64 + c * 8 + t + 4] : 0.0f;
        kb0[c] = __float_as_uint(v0);
        kb1[c] = __float_as_uint(v1);
    }

    const float* __restrict__ memb = memory + (size_t)b * MEM_ELEMS;
    float* tileF = tile + wid * 16 * TSTRIDE;
    float4* tf4 = (float4*)tileF;

    float sum0 = 0.0f, sum1 = 0.0f;   // heads 2t, 2t+1

    for (int j = 0; j < 8; j++) {
        const int n0 = half * 1024 + wid * 16 + j * 128;
#pragma unroll
        for (int i = 0; i < 8; i++) {
            int idx = lane + i * 32;
            int row = idx >> 4, q = idx & 15;
            tf4[row * 17 + q] =
                *(const float4*)(memb + (size_t)(n0 + row) * MM + q * 4);
        }
        __syncwarp();

        float acc[4] = {0.f, 0.f, 0.f, 0.f};
        float ss0 = 0.f, ss1 = 0.f;
#pragma unroll
        for (int c = 0; c < 8; c++) {
            float a0 = tileF[g * TSTRIDE + c * 8 + t];
            float a1 = tileF[(g + 8) * TSTRIDE + c * 8 + t];
            float a2 = tileF[g * TSTRIDE + c * 8 + t + 4];
            float a3 = tileF[(g + 8) * TSTRIDE + c * 8 + t + 4];
            ss0 += a0 * a0 + a2 * a2;
            ss1 += a1 * a1 + a3 * a3;
            unsigned af[4] = {__float_as_uint(a0), __float_as_uint(a1),
                              __float_as_uint(a2), __float_as_uint(a3)};
            MMA_TF32(acc, af, kb0[c], kb1[c]);
        }
        ss0 += __shfl_xor_sync(0xffffffffu, ss0, 1);
        ss0 += __shfl_xor_sync(0xffffffffu, ss0, 2);
        ss1 += __shfl_xor_sync(0xffffffffu, ss1, 1);
        ss1 += __shfl_xor_sync(0xffffffffu, ss1, 2);
        float rn0 = rsqrtf(ss0), rn1 = rsqrtf(ss1);

        float e0 = __expf(acc[0] * rn0);   // head 2t,   row n0+g
        float e1 = __expf(acc[1] * rn0);   // head 2t+1, row n0+g
        float e2 = __expf(acc[2] * rn1);   // head 2t,   row n0+g+8
        float e3 = __expf(acc[3] * rn1);   // head 2t+1, row n0+g+8
        sum0 += e0 + e2;
        sum1 += e1 + e3;

        float* s0 = g_S + ((size_t)b * NN + n0 + g) * 8 + 2 * t;
        float* s1 = g_S + ((size_t)b * NN + n0 + g + 8) * 8 + 2 * t;
        *(float2*)s0 = make_float2(e0, e1);
        *(float2*)s1 = make_float2(e2, e3);
        __syncwarp();
    }

    // reduce sums across the 8 g-lanes sharing t (lane = g*4 + t)
#pragma unroll
    for (int o = 4; o < 32; o <<= 1) {
        sum0 += __shfl_xor_sync(0xffffffffu, sum0, o);
        sum1 += __shfl_xor_sync(0xffffffffu, sum1, o);
    }
    if (g == 0 && t < 3) {
        redp[wid][2 * t]     = sum0;
        redp[wid][2 * t + 1] = sum1;
    }
    __syncthreads();
    if (tid < HH) {
        float s = 0.0f;
#pragma unroll
        for (int wq = 0; wq < 8; wq++) s += redp[wq][tid];
        g_psum[(b * 2 + half) * HH + tid] = s;
    }
}

// ---------------------------------------------------------------------------
// K2c: memory update via mma with m-permuted B fragments (R15, measured 48.4us)
// grid (16, 256), 128 threads, no block barriers.
// ---------------------------------------------------------------------------
__global__ __launch_bounds__(128) void update_kernel(
    const float* __restrict__ memory, float* __restrict__ out_mem)
{
    const int b = (BB - 1) - blockIdx.y;    // reverse: reuse tail of L2 stream
    const int ntile = blockIdx.x;           // 0..15, 128 rows each
    const int tid = threadIdx.x, wid = tid >> 5, lane = tid & 31;
    const int g = lane >> 2, t = lane & 3;

    const float i0t = 1.0f / (g_psum[(b * 2 + 0) * HH + t] +
                              g_psum[(b * 2 + 1) * HH + t]);
    const float i1t = (t < 2)
        ? 1.0f / (g_psum[(b * 2 + 0) * HH + t + 4] +
                  g_psum[(b * 2 + 1) * HH + t + 4])
        : 0.0f;

    const float* __restrict__ eb = g_Es + b * DOUT;
    const float* __restrict__ ab = g_As + b * DOUT;

    const float* __restrict__ memb = memory + (size_t)b * MEM_ELEMS;
    float* __restrict__ outm = out_mem + (size_t)b * MEM_ELEMS;
    const float* __restrict__ wsb = g_S + (size_t)b * NN * 8;

    const int mBase = ((g >> 1) << 2) + (g & 1);

#pragma unroll
    for (int j = 0; j < 2; j++) {
        const int n0 = ntile * 128 + wid * 16 + j * 64;
        const float* ws = wsb + (size_t)n0 * 8;

        unsigned af[4];
        af[0] = __float_as_uint(ws[g * 8 + t] * i0t);
        af[1] = __float_as_uint(ws[(g + 8) * 8 + t] * i0t);
        af[2] = __float_as_uint(ws[g * 8 + t + 4] * i1t);
        af[3] = __float_as_uint(ws[(g + 8) * 8 + t + 4] * i1t);

        const float* mrow0 = memb + (size_t)(n0 + g) * MM;
        const float* mrow1 = memb + (size_t)(n0 + g + 8) * MM;
        float* orow0 = outm + (size_t)(n0 + g) * MM;
        float* orow1 = outm + (size_t)(n0 + g + 8) * MM;

#pragma unroll
        for (int q = 0; q < 4; q++) {
            const int mE = 16 * q + mBase;
            const int mO = mE + 2;

            unsigned eE0 = __float_as_uint(eb[t * 64 + mE]);
            unsigned eO0 = __float_as_uint(eb[t * 64 + mO]);
            unsigned aE0 = __float_as_uint(ab[t * 64 + mE]);
            unsigned aO0 = __float_as_uint(ab[t * 64 + mO]);
            unsigned eE1 = __float_as_uint((t < 2) ? eb[(t + 4) * 64 + mE] : 0.0f);
            unsigned eO1 = __float_as_uint((t < 2) ? eb[(t + 4) * 64 + mO] : 0.0f);
            unsigned aE1 = __float_as_uint((t < 2) ? ab[(t + 4) * 64 + mE] : 0.0f);
            unsigned aO1 = __float_as_uint((t < 2) ? ab[(t + 4) * 64 + mO] : 0.0f);

            float4 mv0 = __ldcs((const float4*)(mrow0 + 16 * q + 4 * t));
            float4 mv1 = __ldcs((const float4*)(mrow1 + 16 * q + 4 * t));

            float erE[4] = {0.f, 0.f, 0.f, 0.f};
            float erO[4] = {0.f, 0.f, 0.f, 0.f};
            float adE[4] = {0.f, 0.f, 0.f, 0.f};
            float adO[4] = {0.f, 0.f, 0.f, 0.f};
            MMA_TF32(erE, af, eE0, eE1);
            MMA_TF32(erO, af, eO0, eO1);
            MMA_TF32(adE, af, aE0, aE1);
            MMA_TF32(adO, af, aO0, aO1);

            float4 o0, o1;
            o0.x = mv0.x + (adE[0] - mv0.x * mv0.x * erE[0]);
            o0.y = mv0.y + (adE[1] - mv0.y * mv0.y * erE[1]);
            o0.z = mv0.z + (adO[0] - mv0.z * mv0.z * erO[0]);
            o0.w = mv0.w + (adO[1] - mv0.w * mv0.w * erO[1]);
            o1.x = mv1.x + (adE[2] - mv1.x * mv1.x * erE[2]);
            o1.y = mv1.y + (adE[3] - mv1.y * mv1.y * erE[3]);
            o1.z = mv1.z + (adO[2] - mv1.z * mv1.z * erO[2]);
            o1.w = mv1.w + (adO[3] - mv1.w * mv1.w * erO[3]);
            __stcs((float4*)(orow0 + 16 * q + 4 * t), o0);
            __stcs((float4*)(orow1 + 16 * q + 4 * t), o1);
        }
    }
}

// ---------------------------------------------------------------------------
// K2d: out_w writer. grid 256, 256 threads. Coalesced reads/writes only.
// ---------------------------------------------------------------------------
__global__ __launch_bounds__(256) void wout_kernel(float* __restrict__ out_w)
{
    const int b = blockIdx.x;
    const int tid = threadIdx.x;

    float inv[HH];
#pragma unroll
    for (int h = 0; h < HH; h++)
        inv[h] = 1.0f / (g_psum[(b * 2 + 0) * HH + h] +
                         g_psum[(b * 2 + 1) * HH + h]);

    const float* __restrict__ wsb = g_S + (size_t)b * NN * 8;
    float* __restrict__ owb = out_w + (size_t)b * (HH * NN);

#pragma unroll
    for (int k = 0; k < 8; k++) {
        int row = tid + k * 256;
        float4 v0 = *(const float4*)(wsb + (size_t)row * 8);
        float2 v1 = *(const float2*)(wsb + (size_t)row * 8 + 4);
        owb[0 * NN + row] = v0.x * inv[0];
        owb[1 * NN + row] = v0.y * inv[1];
        owb[2 * NN + row] = v0.z * inv[2];
        owb[3 * NN + row] = v0.w * inv[3];
        owb[4 * NN + row] = v1.x * inv[4];
        owb[5 * NN + row] = v1.y * inv[5];
    }
}

// ---------------------------------------------------------------------------
extern "C" void kernel_launch(void* const* d_in, const int* in_sizes, int n_in,
                              void* d_out, int out_size)
{
    const float* inputs = (const float*)d_in[0];
    const float* memory = (const float*)d_in[1];
    const float* w      = (const float*)d_in[2];
    const float* Wk     = (const float*)d_in[3];
    const float* bk     = (const float*)d_in[4];
    const float* We     = (const float*)d_in[5];
    const float* be     = (const float*)d_in[6];
    const float* Wa     = (const float*)d_in[7];
    const float* ba     = (const float*)d_in[8];

    float* out     = (float*)d_out;
    float* out_mem = out;                       // new_memory [B,N,M]
    float* out_w   = out + OUT_MEM_TOTAL;       // w_new      [B,H,N]

    cudaFuncSetAttribute(gemm_kernel,
                         cudaFuncAttributeMaxDynamicSharedMemorySize,
                         GEMM_SMEM_BYTES);
    dim3 g1(2, 18, SPLITK);
    gemm_kernel<<<g1, 256, GEMM_SMEM_BYTES>>>(w, inputs, Wk, We, Wa);

    reduce_act_kernel<<<(BB * Y_N) / 256, 256>>>(bk, be, ba);

    scores_kernel<<<dim3(2, BB), 256>>>(memory);

    update_kernel<<<dim3(16, BB), 128>>>(memory, out_mem);

    wout_kernel<<<BB, 256>>>(out_w);
}

// round 17
// speedup vs baseline: 1.1012x; 1.1012x over previous
#include <cuda_runtime.h>
#include <math.h>
#include <stdint.h>

// Problem constants
#define BB    256
#define HH    6
#define NN    2048
#define MM    64
#define DIN   128
#define WFLAT 12288          // H*N
#define DCAT  12416
#define DOUT  384
#define Y_N   1152           // 3*DOUT
#define MEM_ELEMS 131072     // N*M per batch
#define OUT_MEM_TOTAL 33554432  // B*N*M

// GEMM config (R7/R15, measured 56.4us): CTA 128x64, warp 64x32, BKT=32
#define SPLITK 16
#define BKT 32
#define BMT 128
#define BNT 64
#define ASTR 36
#define BSTR 72
#define A_TILE_F (BMT * ASTR)
#define B_TILE_F (BKT * BSTR)
#define GEMM_SMEM_BYTES ((2 * (A_TILE_F + B_TILE_F)) * 4)   // 55296

// Scratch (static device memory; no allocation)
__device__ float g_Ypart[SPLITK * (size_t)BB * Y_N];  // 18.9 MB
__device__ float g_Ks[BB * DOUT];
__device__ float g_Es[BB * DOUT];
__device__ float g_As[BB * DOUT];
__device__ float g_S[(size_t)BB * NN * 8];            // 16.8 MB exp-scores [b][n][8]
__device__ float g_psum[BB * 2 * HH];                 // per-(b,half,h) partial sums

__device__ __forceinline__ unsigned s2u(const void* p) {
    return (unsigned)__cvta_generic_to_shared(p);
}

__device__ __forceinline__ void cpa16(uint32_t dst, const void* src) {
    asm volatile("cp.async.cg.shared.global [%0], [%1], 16;" :: "r"(dst), "l"(src));
}
#define CP_COMMIT() asm volatile("cp.async.commit_group;" ::: "memory")
#define CP_WAIT1()  asm volatile("cp.async.wait_group 1;" ::: "memory")

#define MMA_TF32(c, a, b0, b1)                                                     \
    asm volatile(                                                                  \
        "mma.sync.aligned.m16n8k8.row.col.f32.tf32.tf32.f32 "                      \
        "{%0,%1,%2,%3},{%4,%5,%6,%7},{%8,%9},{%0,%1,%2,%3};"                       \
        : "+f"(c[0]), "+f"(c[1]), "+f"(c[2]), "+f"(c[3])                           \
        : "r"(a[0]), "r"(a[1]), "r"(a[2]), "r"(a[3]), "r"(b0), "r"(b1))

#define LDSM_X4(r, addr)                                                           \
    asm volatile("ldmatrix.sync.aligned.m8n8.x4.shared.b16 {%0,%1,%2,%3}, [%4];"   \
                 : "=r"(r[0]), "=r"(r[1]), "=r"(r[2]), "=r"(r[3]) : "r"(addr))

// ---------------------------------------------------------------------------
// K1: split-K tf32 GEMM (R7/R15 verbatim)
// grid (2, 18, 16), 128 threads. cp.async double-buffered, warp tile 64x32.
// ---------------------------------------------------------------------------
__global__ __launch_bounds__(128) void gemm_kernel(
    const float* __restrict__ xw, const float* __restrict__ xin,
    const float* __restrict__ Wk, const float* __restrict__ We,
    const float* __restrict__ Wa)
{
    extern __shared__ float smf[];
    float* As[2] = {smf, smf + A_TILE_F};
    float* Bs[2] = {smf + 2 * A_TILE_F, smf + 2 * A_TILE_F + B_TILE_F};
    const uint32_t sA32[2] = {s2u(As[0]), s2u(As[1])};
    const uint32_t sB32[2] = {s2u(Bs[0]), s2u(Bs[1])};

    const int tid = threadIdx.x;
    const int mt = blockIdx.x, nt = blockIdx.y, z = blockIdx.z;
    const int m0 = mt * BMT;
    const int mat = nt / 6;
    const int n0col = (nt % 6) * BNT;
    const float* __restrict__ Wp = (mat == 0) ? Wk : ((mat == 1) ? We : Wa);

    const int baseT = z * 24 + min(z, 4);
    const int cnt   = 24 + (z < 4 ? 1 : 0);
    const int k0    = baseT * BKT;

    const int wid = tid >> 5, lane = tid & 31;
    const int g = lane >> 2, t = lane & 3;
    const int wm = (wid & 1) * 64, wn = (wid >> 1) * 32;

    const int aRowOff = (lane & 15) * ASTR + (lane >> 4) * 4;

    const int arow = tid >> 3;
    const int ac4  = (tid & 7) * 4;
    const int brow = tid >> 4;
    const int bc4  = (tid & 15) * 4;

    float acc[4][4][4];
#pragma unroll
    for (int i = 0; i < 4; i++)
#pragma unroll
        for (int j = 0; j < 4; j++)
#pragma unroll
            for (int q = 0; q < 4; q++) acc[i][j][q] = 0.0f;

#define LOADT(it)                                                                  \
    do {                                                                           \
        const int buf = (it) & 1;                                                  \
        int kb = k0 + (it) * BKT;                                                  \
        int kg = kb + ac4;                                                         \
        _Pragma("unroll")                                                          \
        for (int i = 0; i < 8; i++) {                                              \
            int row = arow + i * 16;                                               \
            uint32_t dst = sA32[buf] + 4u * (row * ASTR + ac4);                    \
            const float* src = (kg < WFLAT)                                        \
                ? (xw + (size_t)(m0 + row) * WFLAT + kg)                           \
                : (xin + (size_t)(m0 + row) * DIN + (kg - WFLAT));                 \
            cpa16(dst, src);                                                       \
        }                                                                          \
        _Pragma("unroll")                                                          \
        for (int i = 0; i < 4; i++) {                                              \
            int kr = brow + i * 8;                                                 \
            uint32_t dst = sB32[buf] + 4u * (kr * BSTR + bc4);                     \
            cpa16(dst, Wp + (size_t)(kb + kr) * DOUT + n0col + bc4);               \
        }                                                                          \
    } while (0)

    LOADT(0);
    CP_COMMIT();
    if (cnt > 1) LOADT(1);
    CP_COMMIT();

    for (int it = 0; it < cnt; ++it) {
        CP_WAIT1();
        __syncthreads();

        const int bf = it & 1;
        const uint32_t sA = sA32[bf];
        const float* __restrict__ Bsf = Bs[bf];
#pragma unroll
        for (int ko = 0; ko < BKT; ko += 8) {
            unsigned af[4][4];
#pragma unroll
            for (int mf = 0; mf < 4; mf++) {
                unsigned addr = sA + 4u * ((wm + mf * 16) * ASTR + aRowOff + ko);
                LDSM_X4(af[mf], addr);
            }
            unsigned bfr[4][2];
#pragma unroll
            for (int nf = 0; nf < 4; nf++) {
                int c0 = wn + nf * 8 + g;
                bfr[nf][0] = __float_as_uint(Bsf[(ko + t) * BSTR + c0]);
                bfr[nf][1] = __float_as_uint(Bsf[(ko + t + 4) * BSTR + c0]);
            }
#pragma unroll
            for (int mf = 0; mf < 4; mf++)
#pragma unroll
                for (int nf = 0; nf < 4; nf++)
                    MMA_TF32(acc[mf][nf], af[mf], bfr[nf][0], bfr[nf][1]);
        }

        __syncthreads();
        if (it + 2 < cnt) LOADT(it + 2);
        CP_COMMIT();
    }

    float* yp = g_Ypart + (size_t)z * (BB * Y_N);
#pragma unroll
    for (int mf = 0; mf < 4; mf++) {
#pragma unroll
        for (int nf = 0; nf < 4; nf++) {
            int row = m0 + wm + mf * 16 + g;
            int col = nt * BNT + wn + nf * 8 + 2 * t;
            float2 v0 = make_float2(acc[mf][nf][0], acc[mf][nf][1]);
            float2 v1 = make_float2(acc[mf][nf][2], acc[mf][nf][3]);
            *(float2*)(yp + (size_t)row * Y_N + col) = v0;
            *(float2*)(yp + (size_t)(row + 8) * Y_N + col) = v1;
        }
    }
#undef LOADT
}

// ---------------------------------------------------------------------------
// K1b: reduce split-K partials (float4), add bias, sigmoid for e/a.
// grid 288, 256 threads. A float4 never straddles a matrix boundary.
// ---------------------------------------------------------------------------
__global__ void reduce_act_kernel(const float* __restrict__ bk,
                                  const float* __restrict__ be,
                                  const float* __restrict__ ba)
{
    const int v = blockIdx.x * blockDim.x + threadIdx.x;   // < 73728
    const float4* yp4 = (const float4*)g_Ypart;

    float4 s = make_float4(0.f, 0.f, 0.f, 0.f);
#pragma unroll
    for (int z = 0; z < SPLITK; z++) {
        float4 p = yp4[(size_t)z * (BB * Y_N / 4) + v];
        s.x += p.x; s.y += p.y; s.z += p.z; s.w += p.w;
    }
    const int e0 = v * 4;
    const int row = e0 / Y_N;
    const int col = e0 - row * Y_N;
    const int mat = col / DOUT;
    const int c = col - mat * DOUT;

    if (mat == 0) {
        float4 bv = *(const float4*)(bk + c);
        s.x += bv.x; s.y += bv.y; s.z += bv.z; s.w += bv.w;
        *(float4*)(g_Ks + row * DOUT + c) = s;
    } else if (mat == 1) {
        float4 bv = *(const float4*)(be + c);
        float4 o;
        o.x = 1.0f / (1.0f + __expf(-(s.x + bv.x)));
        o.y = 1.0f / (1.0f + __expf(-(s.y + bv.y)));
        o.z = 1.0f / (1.0f + __expf(-(s.z + bv.z)));
        o.w = 1.0f / (1.0f + __expf(-(s.w + bv.w)));
        *(float4*)(g_Es + row * DOUT + c) = o;
    } else {
        float4 bv = *(const float4*)(ba + c);
        float4 o;
        o.x = 1.0f / (1.0f + __expf(-(s.x + bv.x)));
        o.y = 1.0f / (1.0f + __expf(-(s.y + bv.y)));
        o.z = 1.0f / (1.0f + __expf(-(s.z + bv.z)));
        o.w = 1.0f / (1.0f + __expf(-(s.w + bv.w)));
        *(float4*)(g_As + row * DOUT + c) = o;
    }
}

// ---------------------------------------------------------------------------
// K2a: exp(cosine scores) -> g_S[b][n][8], plus per-(b,half,head) sums.
// grid (2, 256), 256 threads (8 warps), ~36 KB smem (R15 verbatim)
// ---------------------------------------------------------------------------
#define TSTRIDE 68
__global__ __launch_bounds__(256) void scores_kernel(
    const float* __restrict__ memory)
{
    __shared__ float kn[DOUT];
    __shared__ float tile[8 * 16 * TSTRIDE];
    __shared__ float redp[8][8];   // [warp][head]

    const int b = blockIdx.y;
    const int half = blockIdx.x;
    const int tid = threadIdx.x, wid = tid >> 5, lane = tid & 31;
    const int g = lane >> 2, t = lane & 3;

    if (wid < HH) {
        float k0 = g_Ks[b * DOUT + wid * 64 + 2 * lane];
        float k1 = g_Ks[b * DOUT + wid * 64 + 2 * lane + 1];
        float ss = k0 * k0 + k1 * k1;
#pragma unroll
        for (int o = 16; o > 0; o >>= 1) ss += __shfl_xor_sync(0xffffffffu, ss, o);
        float rn = rsqrtf(ss);
        kn[wid * 64 + 2 * lane]     = k0 * rn;
        kn[wid * 64 + 2 * lane + 1] = k1 * rn;
    }
    __syncthreads();

    unsigned kb0[8], kb1[8];
#pragma unroll
    for (int c = 0; c < 8; c++) {
        float v0 = (g < HH) ? kn[g * 64 + c * 8 + t] : 0.0f;
        float v1 = (g < HH) ? kn[g * 64 + c * 8 + t + 4] : 0.0f;
        kb0[c] = __float_as_uint(v0);
        kb1[c] = __float_as_uint(v1);
    }

    const float* __restrict__ memb = memory + (size_t)b * MEM_ELEMS;
    float* tileF = tile + wid * 16 * TSTRIDE;
    float4* tf4 = (float4*)tileF;

    float sum0 = 0.0f, sum1 = 0.0f;

    for (int j = 0; j < 8; j++) {
        const int n0 = half * 1024 + wid * 16 + j * 128;
#pragma unroll
        for (int i = 0; i < 8; i++) {
            int idx = lane + i * 32;
            int row = idx >> 4, q = idx & 15;
            tf4[row * 17 + q] =
                *(const float4*)(memb + (size_t)(n0 + row) * MM + q * 4);
        }
        __syncwarp();

        float acc[4] = {0.f, 0.f, 0.f, 0.f};
        float ss0 = 0.f, ss1 = 0.f;
#pragma unroll
        for (int c = 0; c < 8; c++) {
            float a0 = tileF[g * TSTRIDE + c * 8 + t];
            float a1 = tileF[(g + 8) * TSTRIDE + c * 8 + t];
            float a2 = tileF[g * TSTRIDE + c * 8 + t + 4];
            float a3 = tileF[(g + 8) * TSTRIDE + c * 8 + t + 4];
            ss0 += a0 * a0 + a2 * a2;
            ss1 += a1 * a1 + a3 * a3;
            unsigned af[4] = {__float_as_uint(a0), __float_as_uint(a1),
                              __float_as_uint(a2), __float_as_uint(a3)};
            MMA_TF32(acc, af, kb0[c], kb1[c]);
        }
        ss0 += __shfl_xor_sync(0xffffffffu, ss0, 1);
        ss0 += __shfl_xor_sync(0xffffffffu, ss0, 2);
        ss1 += __shfl_xor_sync(0xffffffffu, ss1, 1);
        ss1 += __shfl_xor_sync(0xffffffffu, ss1, 2);
        float rn0 = rsqrtf(ss0), rn1 = rsqrtf(ss1);

        float e0 = __expf(acc[0] * rn0);
        float e1 = __expf(acc[1] * rn0);
        float e2 = __expf(acc[2] * rn1);
        float e3 = __expf(acc[3] * rn1);
        sum0 += e0 + e2;
        sum1 += e1 + e3;

        float* s0 = g_S + ((size_t)b * NN + n0 + g) * 8 + 2 * t;
        float* s1 = g_S + ((size_t)b * NN + n0 + g + 8) * 8 + 2 * t;
        *(float2*)s0 = make_float2(e0, e1);
        *(float2*)s1 = make_float2(e2, e3);
        __syncwarp();
    }

#pragma unroll
    for (int o = 4; o < 32; o <<= 1) {
        sum0 += __shfl_xor_sync(0xffffffffu, sum0, o);
        sum1 += __shfl_xor_sync(0xffffffffu, sum1, o);
    }
    if (g == 0 && t < 3) {
        redp[wid][2 * t]     = sum0;
        redp[wid][2 * t + 1] = sum1;
    }
    __syncthreads();
    if (tid < HH) {
        float s = 0.0f;
#pragma unroll
        for (int wq = 0; wq < 8; wq++) s += redp[wq][tid];
        g_psum[(b * 2 + half) * HH + tid] = s;
    }
}

// ---------------------------------------------------------------------------
// K2c: memory update via mma with m-permuted B fragments (R15, 48.4us core)
// + fused out_w tail for this CTA's 128 rows (L2-hot g_S, coalesced stores).
// grid (16, 256), 128 threads, no block barriers.
// ---------------------------------------------------------------------------
__global__ __launch_bounds__(128) void update_kernel(
    const float* __restrict__ memory, float* __restrict__ out_mem,
    float* __restrict__ out_w)
{
    const int b = (BB - 1) - blockIdx.y;    // reverse: reuse tail of L2 stream
    const int ntile = blockIdx.x;           // 0..15, 128 rows each
    const int tid = threadIdx.x, wid = tid >> 5, lane = tid & 31;
    const int g = lane >> 2, t = lane & 3;

    float inv[HH];
#pragma unroll
    for (int h = 0; h < HH; h++)
        inv[h] = 1.0f / (g_psum[(b * 2 + 0) * HH + h] +
                         g_psum[(b * 2 + 1) * HH + h]);
    const float i0t = inv[t];
    const float i1t = (t < 2) ? inv[t + 4] : 0.0f;

    const float* __restrict__ eb = g_Es + b * DOUT;
    const float* __restrict__ ab = g_As + b * DOUT;

    const float* __restrict__ memb = memory + (size_t)b * MEM_ELEMS;
    float* __restrict__ outm = out_mem + (size_t)b * MEM_ELEMS;
    const float* __restrict__ wsb = g_S + (size_t)b * NN * 8;

    const int mBase = ((g >> 1) << 2) + (g & 1);

#pragma unroll
    for (int j = 0; j < 2; j++) {
        const int n0 = ntile * 128 + wid * 16 + j * 64;
        const float* ws = wsb + (size_t)n0 * 8;

        unsigned af[4];
        af[0] = __float_as_uint(ws[g * 8 + t] * i0t);
        af[1] = __float_as_uint(ws[(g + 8) * 8 + t] * i0t);
        af[2] = __float_as_uint(ws[g * 8 + t + 4] * i1t);
        af[3] = __float_as_uint(ws[(g + 8) * 8 + t + 4] * i1t);

        const float* mrow0 = memb + (size_t)(n0 + g) * MM;
        const float* mrow1 = memb + (size_t)(n0 + g + 8) * MM;
        float* orow0 = outm + (size_t)(n0 + g) * MM;
        float* orow1 = outm + (size_t)(n0 + g + 8) * MM;

#pragma unroll
        for (int q = 0; q < 4; q++) {
            const int mE = 16 * q + mBase;
            const int mO = mE + 2;

            unsigned eE0 = __float_as_uint(eb[t * 64 + mE]);
            unsigned eO0 = __float_as_uint(eb[t * 64 + mO]);
            unsigned aE0 = __float_as_uint(ab[t * 64 + mE]);
            unsigned aO0 = __float_as_uint(ab[t * 64 + mO]);
            unsigned eE1 = __float_as_uint((t < 2) ? eb[(t + 4) * 64 + mE] : 0.0f);
            unsigned eO1 = __float_as_uint((t < 2) ? eb[(t + 4) * 64 + mO] : 0.0f);
            unsigned aE1 = __float_as_uint((t < 2) ? ab[(t + 4) * 64 + mE] : 0.0f);
            unsigned aO1 = __float_as_uint((t < 2) ? ab[(t + 4) * 64 + mO] : 0.0f);

            float4 mv0 = __ldcs((const float4*)(mrow0 + 16 * q + 4 * t));
            float4 mv1 = __ldcs((const float4*)(mrow1 + 16 * q + 4 * t));

            float erE[4] = {0.f, 0.f, 0.f, 0.f};
            float erO[4] = {0.f, 0.f, 0.f, 0.f};
            float adE[4] = {0.f, 0.f, 0.f, 0.f};
            float adO[4] = {0.f, 0.f, 0.f, 0.f};
            MMA_TF32(erE, af, eE0, eE1);
            MMA_TF32(erO, af, eO0, eO1);
            MMA_TF32(adE, af, aE0, aE1);
            MMA_TF32(adO, af, aO0, aO1);

            float4 o0, o1;
            o0.x = mv0.x + (adE[0] - mv0.x * mv0.x * erE[0]);
            o0.y = mv0.y + (adE[1] - mv0.y * mv0.y * erE[1]);
            o0.z = mv0.z + (adO[0] - mv0.z * mv0.z * erO[0]);
            o0.w = mv0.w + (adO[1] - mv0.w * mv0.w * erO[1]);
            o1.x = mv1.x + (adE[2] - mv1.x * mv1.x * erE[2]);
            o1.y = mv1.y + (adE[3] - mv1.y * mv1.y * erE[3]);
            o1.z = mv1.z + (adO[2] - mv1.z * mv1.z * erO[2]);
            o1.w = mv1.w + (adO[3] - mv1.w * mv1.w * erO[3]);
            __stcs((float4*)(orow0 + 16 * q + 4 * t), o0);
            __stcs((float4*)(orow1 + 16 * q + 4 * t), o1);
        }
    }

    // ---- fused out_w tail: this CTA's 128 rows (g_S rows are L2-hot) ----
    {
        const int rowt = ntile * 128 + tid;
        float4 v0 = *(const float4*)(wsb + (size_t)rowt * 8);
        float2 v1 = *(const float2*)(wsb + (size_t)rowt * 8 + 4);
        float* owb = out_w + (size_t)b * (HH * NN);
        owb[0 * NN + rowt] = v0.x * inv[0];
        owb[1 * NN + rowt] = v0.y * inv[1];
        owb[2 * NN + rowt] = v0.z * inv[2];
        owb[3 * NN + rowt] = v0.w * inv[3];
        owb[4 * NN + rowt] = v1.x * inv[4];
        owb[5 * NN + rowt] = v1.y * inv[5];
    }
}

// ---------------------------------------------------------------------------
extern "C" void kernel_launch(void* const* d_in, const int* in_sizes, int n_in,
                              void* d_out, int out_size)
{
    const float* inputs = (const float*)d_in[0];
    const float* memory = (const float*)d_in[1];
    const float* w      = (const float*)d_in[2];
    const float* Wk     = (const float*)d_in[3];
    const float* bk     = (const float*)d_in[4];
    const float* We     = (const float*)d_in[5];
    const float* be     = (const float*)d_in[6];
    const float* Wa     = (const float*)d_in[7];
    const float* ba     = (const float*)d_in[8];

    float* out     = (float*)d_out;
    float* out_mem = out;                       // new_memory [B,N,M]
    float* out_w   = out + OUT_MEM_TOTAL;       // w_new      [B,H,N]

    cudaFuncSetAttribute(gemm_kernel,
                         cudaFuncAttributeMaxDynamicSharedMemorySize,
                         GEMM_SMEM_BYTES);
    dim3 g1(2, 18, SPLITK);
    gemm_kernel<<<g1, 128, GEMM_SMEM_BYTES>>>(w, inputs, Wk, We, Wa);

    reduce_act_kernel<<<(BB * Y_N / 4) / 256, 256>>>(bk, be, ba);

    scores_kernel<<<dim3(2, BB), 256>>>(memory);

    update_kernel<<<dim3(16, BB), 128>>>(memory, out_mem, out_w);
}